// round 3
// baseline (speedup 1.0000x reference)
#include <cuda_runtime.h>
#include <cstdint>
#include <cstddef>

// 3-layer LSTM (H=64), S=2048, B=512, FC(64->2).
// Round 3 structure:
//  - Input projections (Wih @ x + bias) hoisted out of the recurrence into a
//    time-parallel GEMM kernel (lstm_proj) -> g_xp (1GB), since they have no
//    sequential dependency. Recurrence keeps only Whh @ h.
//  - Both kernels use a row-pair layout: thread owns gate rows (g2, g2+128)
//    and one K-half, so each LDS.128 of h feeds 4 fma2 (2 rows x f32x2),
//    removing the LDS/FMA co-bind seen in round 2.
// Sequence: rec L0 (x->bufA) ; proj1 (bufA->xp) ; rec L1 (xp->bufB) ;
//           proj2 (bufB->xp) ; rec L2 (xp -> FC -> out).

#define SQ   2048
#define BB   512
#define HID  64
#define NG   256
#define BT   4
#define HSTR 36     // h half-stride (32 data + 4 pad): kh halves 4 banks apart
#define GST  268    // gsm row stride; rows >=128 offset +4 to dodge kh conflict

static __device__ float g_bufA[(size_t)SQ * BB * HID];   // 256 MB
static __device__ float g_bufB[(size_t)SQ * BB * HID];   // 256 MB
static __device__ float g_xp  [(size_t)SQ * BB * NG];    // 1 GB

__device__ __forceinline__ unsigned long long fma2(unsigned long long a,
                                                   unsigned long long b,
                                                   unsigned long long c) {
    unsigned long long d;
    asm("fma.rn.f32x2 %0, %1, %2, %3;" : "=l"(d) : "l"(a), "l"(b), "l"(c));
    return d;
}
__device__ __forceinline__ float lohi(unsigned long long u) {
    union { unsigned long long v; float2 f; } c; c.v = u;
    return c.f.x + c.f.y;
}
__device__ __forceinline__ float ex2a(float x) {
    float y; asm("ex2.approx.f32 %0, %1;" : "=f"(y) : "f"(x)); return y;
}
__device__ __forceinline__ float rcpa(float x) {
    float y; asm("rcp.approx.f32 %0, %1;" : "=f"(y) : "f"(x)); return y;
}
__device__ __forceinline__ float sigf(float x) {
    return rcpa(1.0f + ex2a(-1.4426950408889634f * x));
}
__device__ __forceinline__ float tanh_(float x) {
    return 2.0f * rcpa(1.0f + ex2a(-2.8853900817779268f * x)) - 1.0f;
}

// ---------------------------------------------------------------------------
// Recurrence kernel. 128 CTAs x 512 threads, BT=4 batch rows per CTA.
// Thread: bh=tid&1 (batch half), kh=(tid>>1)&1 (K half), g2=tid>>2 (row pair).
// Computes partial gate sums for rows {g2, g2+128} x batches {2bh, 2bh+1};
// shfl.xor(2) merges K halves; kh selects which row this thread activates.
// ---------------------------------------------------------------------------
template <bool L0, bool XP, int DSTB, bool FINAL>
__global__ void __launch_bounds__(512, 1)
lstm_rec(const float* __restrict__ xin,
         const float* __restrict__ Wih, const float* __restrict__ Whh,
         const float* __restrict__ bih, const float* __restrict__ bhh,
         const float* __restrict__ fcw, const float* __restrict__ fcb,
         float* __restrict__ out)
{
    __shared__ __align__(16) float hs[BT][2][HSTR];
    __shared__ float gsm[BT][GST];
    __shared__ float xsm[BT][4];           // L0 only (input width 4)

    const int tid  = threadIdx.x;
    const int bh   = tid & 1;
    const int kh   = (tid >> 1) & 1;
    const int g2   = tid >> 2;             // 0..127
    const int rsel = g2 + 128 * kh;        // row this thread activates
    const int b0   = blockIdx.x * BT;
    const int bA   = 2 * bh, bBt = 2 * bh + 1;

    // Whh rows g2 / g2+128, K-half kh (32 floats each), packed f32x2
    unsigned long long w0_[16], w1_[16];
#pragma unroll
    for (int k2 = 0; k2 < 16; k2++) {
        w0_[k2] = *(const unsigned long long*)(Whh + (size_t)g2 * HID + kh * 32 + 2 * k2);
        w1_[k2] = *(const unsigned long long*)(Whh + (size_t)(g2 + 128) * HID + kh * 32 + 2 * k2);
    }
    unsigned long long wi0[2], wi1[2];
    if (L0) {   // input weights (4 cols) — attributed to kh==0 half
        wi0[0] = *(const unsigned long long*)(Wih + (size_t)g2 * 4);
        wi0[1] = *(const unsigned long long*)(Wih + (size_t)g2 * 4 + 2);
        wi1[0] = *(const unsigned long long*)(Wih + (size_t)(g2 + 128) * 4);
        wi1[1] = *(const unsigned long long*)(Wih + (size_t)(g2 + 128) * 4 + 2);
    }
    const float bias = L0 ? (bih[rsel] + bhh[rsel]) : 0.0f;   // XP: bias in xp
    const int   gt   = rsel >> 6;          // 2 -> tanh gate
    const int   gidx = g2 + 132 * kh;      // gsm column for rsel

    // update mapping (threads 0..255)
    const int ub = (tid >> 6) & 3, uj = tid & 63;
    float c_state = 0.0f;
    if (tid < 256) hs[ub][uj >> 5][uj & 31] = 0.0f;

    // prefetch step-0 inputs
    float xq0 = 0.f, xq1 = 0.f, x0q = 0.f;
    if (XP) {
        xq0 = g_xp[((size_t)0 * BB + b0 + bA ) * NG + rsel];
        xq1 = g_xp[((size_t)0 * BB + b0 + bBt) * NG + rsel];
    }
    if (L0 && tid < 16)
        x0q = xin[(size_t)(b0 + (tid >> 2)) * (SQ * 4) + (tid & 3)];

    for (int t = 0; t < SQ; t++) {
        if (L0) { if (tid < 16) xsm[tid >> 2][tid & 3] = x0q; }
        __syncthreads();                   // (A) hs update + xsm visible

        // prefetch t+1 (covered by the FMA block below)
        float xn0 = 0.f, xn1 = 0.f, x0n = 0.f;
        if (t + 1 < SQ) {
            if (XP) {
                xn0 = g_xp[((size_t)(t + 1) * BB + b0 + bA ) * NG + rsel];
                xn1 = g_xp[((size_t)(t + 1) * BB + b0 + bBt) * NG + rsel];
            }
            if (L0 && tid < 16)
                x0n = xin[(size_t)(b0 + (tid >> 2)) * (SQ * 4) + (size_t)(t + 1) * 4 + (tid & 3)];
        }

        // partial gate sums: rows (g2, g2+128) x batches (bA, bBt), K-half kh
        unsigned long long a00 = 0ULL, a01 = 0ULL, a10 = 0ULL, a11 = 0ULL;
#pragma unroll
        for (int k4 = 0; k4 < 8; k4++) {
            unsigned long long W0a = w0_[2 * k4], W0b = w0_[2 * k4 + 1];
            unsigned long long W1a = w1_[2 * k4], W1b = w1_[2 * k4 + 1];
            ulonglong2 h0 = *(const ulonglong2*)(&hs[bA ][kh][4 * k4]);
            ulonglong2 h1 = *(const ulonglong2*)(&hs[bBt][kh][4 * k4]);
            a00 = fma2(W0a, h0.x, a00); a00 = fma2(W0b, h0.y, a00);
            a01 = fma2(W0a, h1.x, a01); a01 = fma2(W0b, h1.y, a01);
            a10 = fma2(W1a, h0.x, a10); a10 = fma2(W1b, h0.y, a10);
            a11 = fma2(W1a, h1.x, a11); a11 = fma2(W1b, h1.y, a11);
        }
        if (L0 && kh == 0) {
            ulonglong2 xv0 = *(const ulonglong2*)(&xsm[bA ][0]);
            ulonglong2 xv1 = *(const ulonglong2*)(&xsm[bBt][0]);
            a00 = fma2(wi0[0], xv0.x, a00); a00 = fma2(wi0[1], xv0.y, a00);
            a01 = fma2(wi0[0], xv1.x, a01); a01 = fma2(wi0[1], xv1.y, a01);
            a10 = fma2(wi1[0], xv0.x, a10); a10 = fma2(wi1[1], xv0.y, a10);
            a11 = fma2(wi1[0], xv1.x, a11); a11 = fma2(wi1[1], xv1.y, a11);
        }

        float s00 = lohi(a00), s01 = lohi(a01), s10 = lohi(a10), s11 = lohi(a11);
        s00 += __shfl_xor_sync(0xffffffffu, s00, 2);
        s01 += __shfl_xor_sync(0xffffffffu, s01, 2);
        s10 += __shfl_xor_sync(0xffffffffu, s10, 2);
        s11 += __shfl_xor_sync(0xffffffffu, s11, 2);

        float v0 = (kh ? s10 : s00) + bias + (XP ? xq0 : 0.f);
        float v1 = (kh ? s11 : s01) + bias + (XP ? xq1 : 0.f);
        gsm[bA ][gidx] = (gt == 2) ? tanh_(v0) : sigf(v0);
        gsm[bBt][gidx] = (gt == 2) ? tanh_(v1) : sigf(v1);

        xq0 = xn0; xq1 = xn1;
        if (L0 && tid < 16) x0q = x0n;
        __syncthreads();                   // (B) gates visible

        if (tid < 256) {
            float iv = gsm[ub][uj];
            float fv = gsm[ub][64 + uj];
            float gv = gsm[ub][132 + uj];
            float ov = gsm[ub][196 + uj];
            c_state = fv * c_state + iv * gv;
            float h = ov * tanh_(c_state);
            hs[ub][uj >> 5][uj & 31] = h;
            if (DSTB >= 0) {
                float* dst = (DSTB == 0) ? g_bufA : g_bufB;
                dst[((size_t)t * BB + b0 + ub) * HID + uj] = h;
            }
        }
    }

    if (FINAL) {
        __syncthreads();
        if (tid < BT * 2) {
            int b = tid >> 1, o = tid & 1;
            float s = fcb[o];
#pragma unroll
            for (int j = 0; j < HID; j++)
                s += hs[b][j >> 5][j & 31] * fcw[o * HID + j];
            out[(b0 + b) * 2 + o] = s;
        }
    }
}

// ---------------------------------------------------------------------------
// Projection GEMM: xp[row][g] = Wih[g,:] . src[row,:] + bih[g] + bhh[g]
// rows = S*B (time-parallel). 512 threads: kh=tid&1, rg=(tid>>1)&1,
// g2=tid>>2. Thread: rows (g2, g2+128) x K-half kh x 4 data rows (rg half
// of an 8-row block). shfl.xor(1) merges K halves.
// ---------------------------------------------------------------------------
#define PROJ_CTAS 1024
#define ROWS_PER_CTA ((SQ * BB) / PROJ_CTAS)   // 1024
#define RBLK 8

template <int SRCB>
__global__ void __launch_bounds__(512, 1)
lstm_proj(const float* __restrict__ Wih,
          const float* __restrict__ bih, const float* __restrict__ bhh)
{
    const float* src = (SRCB == 0) ? g_bufA : g_bufB;
    __shared__ __align__(16) float xr[RBLK][2][HSTR];   // [row][kh][32+pad]

    const int tid = threadIdx.x;
    const int kh  = tid & 1;
    const int rg  = (tid >> 1) & 1;
    const int g2  = tid >> 2;
    const int rsel = g2 + 128 * kh;

    unsigned long long w0_[16], w1_[16];
#pragma unroll
    for (int k2 = 0; k2 < 16; k2++) {
        w0_[k2] = *(const unsigned long long*)(Wih + (size_t)g2 * HID + kh * 32 + 2 * k2);
        w1_[k2] = *(const unsigned long long*)(Wih + (size_t)(g2 + 128) * HID + kh * 32 + 2 * k2);
    }
    const float bias = bih[rsel] + bhh[rsel];

    const size_t row0 = (size_t)blockIdx.x * ROWS_PER_CTA;

    for (int it = 0; it < ROWS_PER_CTA / RBLK; it++) {
        const size_t rb = row0 + (size_t)it * RBLK;
        // cooperative load: 8 rows x 64 floats = 256 ull, threads 0..255
        if (tid < 256) {
            unsigned long long v =
                *(const unsigned long long*)(src + rb * HID + 2 * (size_t)tid);
            int row = tid >> 5, c2 = tid & 31;          // 2 floats at col 2*c2
            *(unsigned long long*)(&xr[row][c2 >> 4][(2 * c2) & 31]) = v;
        }
        __syncthreads();

        unsigned long long a0[4] = {0ULL, 0ULL, 0ULL, 0ULL};
        unsigned long long a1[4] = {0ULL, 0ULL, 0ULL, 0ULL};
#pragma unroll
        for (int k4 = 0; k4 < 8; k4++) {
            unsigned long long W0a = w0_[2 * k4], W0b = w0_[2 * k4 + 1];
            unsigned long long W1a = w1_[2 * k4], W1b = w1_[2 * k4 + 1];
#pragma unroll
            for (int rr = 0; rr < 4; rr++) {
                ulonglong2 hv = *(const ulonglong2*)(&xr[rg * 4 + rr][kh][4 * k4]);
                a0[rr] = fma2(W0a, hv.x, a0[rr]); a0[rr] = fma2(W0b, hv.y, a0[rr]);
                a1[rr] = fma2(W1a, hv.x, a1[rr]); a1[rr] = fma2(W1b, hv.y, a1[rr]);
            }
        }
#pragma unroll
        for (int rr = 0; rr < 4; rr++) {
            float s0 = lohi(a0[rr]);
            float s1 = lohi(a1[rr]);
            s0 += __shfl_xor_sync(0xffffffffu, s0, 1);
            s1 += __shfl_xor_sync(0xffffffffu, s1, 1);
            float v = (kh ? s1 : s0) + bias;
            g_xp[(rb + rg * 4 + rr) * NG + rsel] = v;
        }
        __syncthreads();   // xr reuse
    }
}

extern "C" void kernel_launch(void* const* d_in, const int* in_sizes, int n_in,
                              void* d_out, int out_size)
{
    (void)in_sizes; (void)n_in; (void)out_size;
    const float* x    = (const float*)d_in[0];
    const float* Wih0 = (const float*)d_in[1];
    const float* Whh0 = (const float*)d_in[2];
    const float* bih0 = (const float*)d_in[3];
    const float* bhh0 = (const float*)d_in[4];
    const float* Wih1 = (const float*)d_in[5];
    const float* Whh1 = (const float*)d_in[6];
    const float* bih1 = (const float*)d_in[7];
    const float* bhh1 = (const float*)d_in[8];
    const float* Wih2 = (const float*)d_in[9];
    const float* Whh2 = (const float*)d_in[10];
    const float* bih2 = (const float*)d_in[11];
    const float* bhh2 = (const float*)d_in[12];
    const float* fc_w = (const float*)d_in[13];
    const float* fc_b = (const float*)d_in[14];
    float* out = (float*)d_out;

    dim3 rgrid(BB / BT), rblock(512);
    dim3 pgrid(PROJ_CTAS), pblock(512);

    // L0 recurrence: x -> bufA
    lstm_rec<true, false, 0, false><<<rgrid, rblock>>>(
        x, Wih0, Whh0, bih0, bhh0, nullptr, nullptr, nullptr);
    // proj for L1: bufA -> xp
    lstm_proj<0><<<pgrid, pblock>>>(Wih1, bih1, bhh1);
    // L1 recurrence: xp -> bufB
    lstm_rec<false, true, 1, false><<<rgrid, rblock>>>(
        nullptr, nullptr, Whh1, nullptr, nullptr, nullptr, nullptr, nullptr);
    // proj for L2: bufB -> xp
    lstm_proj<1><<<pgrid, pblock>>>(Wih2, bih2, bhh2);
    // L2 recurrence: xp -> FC -> out
    lstm_rec<false, true, -1, true><<<rgrid, rblock>>>(
        nullptr, nullptr, Whh2, nullptr, nullptr, fc_w, fc_b, out);
}

// round 4
// speedup vs baseline: 2.0073x; 2.0073x over previous
#include <cuda_runtime.h>
#include <cstdint>
#include <cstddef>

// 3-layer LSTM (H=64), S=2048, B=512, FC(64->2).
// rec: persistent per-CTA recurrence (Whh only), 1 barrier/step,
//      double-buffered h, butterfly gate merge, local c/h update.
// proj: time-parallel GEMM computing Wih@h + bias into g_xp with
//       gate-permuted layout col = 4*j + gate_type (coalesced both sides).

#define SQ   2048
#define BB   512
#define HID  64
#define BT   4
#define HP   72            // padded h row stride (conflict-free with k=16m+4kq)

static __device__ float g_bufA[(size_t)SQ * BB * HID];    // 256 MB
static __device__ float g_bufB[(size_t)SQ * BB * HID];    // 256 MB
static __device__ float g_xp  [(size_t)SQ * BB * 256];    // 1 GB, permuted cols

__device__ __forceinline__ unsigned long long fma2(unsigned long long a,
                                                   unsigned long long b,
                                                   unsigned long long c) {
    unsigned long long d;
    asm("fma.rn.f32x2 %0, %1, %2, %3;" : "=l"(d) : "l"(a), "l"(b), "l"(c));
    return d;
}
__device__ __forceinline__ float lohi(unsigned long long u) {
    union { unsigned long long v; float2 f; } c; c.v = u;
    return c.f.x + c.f.y;
}
__device__ __forceinline__ float ex2a(float x) {
    float y; asm("ex2.approx.f32 %0, %1;" : "=f"(y) : "f"(x)); return y;
}
__device__ __forceinline__ float rcpa(float x) {
    float y; asm("rcp.approx.f32 %0, %1;" : "=f"(y) : "f"(x)); return y;
}
__device__ __forceinline__ float sigf(float x) {
    return rcpa(1.0f + ex2a(-1.4426950408889634f * x));
}
__device__ __forceinline__ float tanh_(float x) {
    return 2.0f * rcpa(1.0f + ex2a(-2.8853900817779268f * x)) - 1.0f;
}
// value of gate g lives in: (g^kq)==0 -> a, ==1 -> x1, ==2 -> x2, ==3 -> x3
__device__ __forceinline__ float pick(int idx, float a, float x1, float x2, float x3) {
    return idx == 0 ? a : (idx == 1 ? x1 : (idx == 2 ? x2 : x3));
}

// ---------------------------------------------------------------------------
// Recurrence. grid=128 (BT=4 batches/CTA), block=512.
// Thread: j = tid>>3 (0..63), kq = (tid>>1)&3 (lane bits 1-2), bh = tid&1.
// Owns gate rows {j, 64+j, 128+j, 192+j}, K subset {16m+4kq+0..3, m=0..3},
// batches {2bh, 2bh+1}. One __syncthreads per step.
// MODE: 0 = layer0 (x inline, write bufA), 1 = mid (xp in, write bufB),
//       2 = final (xp in, FC out).
// ---------------------------------------------------------------------------
template <int MODE>
__global__ void __launch_bounds__(512, 1)
lstm_rec(const float* __restrict__ xin,
         const float* __restrict__ Wih, const float* __restrict__ Whh,
         const float* __restrict__ bih, const float* __restrict__ bhh,
         const float* __restrict__ fcw, const float* __restrict__ fcb,
         float* __restrict__ out)
{
    __shared__ __align__(16) float hs[2][BT][HP];
    __shared__ float xsm[2][BT * 4];                 // MODE 0 only

    const int tid = threadIdx.x;
    const int j   = tid >> 3;
    const int kq  = (tid >> 1) & 3;
    const int bh  = tid & 1;
    const int b0  = blockIdx.x * BT;
    const int bl0 = 2 * bh;                           // local batches bl0, bl0+1

    // Whh[row=64g+j][k=16m+4kq .. +3], packed f32x2: w[g][2m], w[g][2m+1]
    unsigned long long w[4][8];
#pragma unroll
    for (int g = 0; g < 4; g++)
#pragma unroll
        for (int m = 0; m < 4; m++) {
            const float* p = Whh + (size_t)(64 * g + j) * HID + 16 * m + 4 * kq;
            w[g][2 * m]     = *(const unsigned long long*)(p);
            w[g][2 * m + 1] = *(const unsigned long long*)(p + 2);
        }

    float4 wi = make_float4(0.f, 0.f, 0.f, 0.f);
    float  biask = 0.f;
    if (MODE == 0) {
        wi = *(const float4*)(Wih + (size_t)(64 * kq + j) * 4);
        biask = bih[64 * kq + j] + bhh[64 * kq + j];
    }

    float c0 = 0.f, c1 = 0.f;
    if (kq == 0) { hs[0][bl0][j] = 0.f; hs[0][bl0 + 1][j] = 0.f; }

    // step-0 inputs
    float xpc0 = 0.f, xpc1 = 0.f;
    if (MODE != 0) {
        xpc0 = g_xp[((size_t)0 * BB + b0 + bl0)     * 256 + 4 * j + kq];
        xpc1 = g_xp[((size_t)0 * BB + b0 + bl0 + 1) * 256 + 4 * j + kq];
    } else if (tid < 16) {
        xsm[0][tid] = xin[(size_t)(b0 + (tid >> 2)) * (SQ * 4) + (tid & 3)];
    }
    __syncthreads();

    float* dst = (MODE == 0) ? g_bufA : g_bufB;

    for (int t = 0; t < SQ; t++) {
        const int p = t & 1;

        // prefetch t+1 input (covered by GEMM below)
        float xpn0 = 0.f, xpn1 = 0.f, xnx = 0.f;
        if (t + 1 < SQ) {
            if (MODE != 0) {
                xpn0 = g_xp[((size_t)(t + 1) * BB + b0 + bl0)     * 256 + 4 * j + kq];
                xpn1 = g_xp[((size_t)(t + 1) * BB + b0 + bl0 + 1) * 256 + 4 * j + kq];
            } else if (tid < 16) {
                xnx = xin[(size_t)(b0 + (tid >> 2)) * (SQ * 4) + (size_t)(t + 1) * 4 + (tid & 3)];
            }
        }

        // ---- GEMM: acc[g][i] over this thread's K subset ----
        unsigned long long acc[4][2];
#pragma unroll
        for (int g = 0; g < 4; g++) { acc[g][0] = 0ULL; acc[g][1] = 0ULL; }
#pragma unroll
        for (int m = 0; m < 4; m++) {
            ulonglong2 h0 = *(const ulonglong2*)(&hs[p][bl0][16 * m + 4 * kq]);
            ulonglong2 h1 = *(const ulonglong2*)(&hs[p][bl0 + 1][16 * m + 4 * kq]);
#pragma unroll
            for (int g = 0; g < 4; g++) {
                acc[g][0] = fma2(w[g][2 * m], h0.x, acc[g][0]);
                acc[g][0] = fma2(w[g][2 * m + 1], h0.y, acc[g][0]);
                acc[g][1] = fma2(w[g][2 * m], h1.x, acc[g][1]);
                acc[g][1] = fma2(w[g][2 * m + 1], h1.y, acc[g][1]);
            }
        }

        // ---- butterfly-sum over kq (lane bits 1,2): all lanes get full sums
        float s[4][2];
#pragma unroll
        for (int g = 0; g < 4; g++)
#pragma unroll
            for (int i = 0; i < 2; i++) {
                float v = lohi(acc[g][i]);
                v += __shfl_xor_sync(0xffffffffu, v, 2);
                v += __shfl_xor_sync(0xffffffffu, v, 4);
                s[g][i] = v;
            }

        // ---- duty gate kq: pre-activation (+xp or inline x-proj) ----
        float sd0 = pick(kq, s[0][0], s[1][0], s[2][0], s[3][0]);
        float sd1 = pick(kq, s[0][1], s[1][1], s[2][1], s[3][1]);
        float pre0, pre1;
        if (MODE == 0) {
            const float* xa = &xsm[p][bl0 * 4];
            const float* xb = &xsm[p][(bl0 + 1) * 4];
            pre0 = sd0 + biask + wi.x * xa[0] + wi.y * xa[1] + wi.z * xa[2] + wi.w * xa[3];
            pre1 = sd1 + biask + wi.x * xb[0] + wi.y * xb[1] + wi.z * xb[2] + wi.w * xb[3];
        } else {
            pre0 = sd0 + xpc0;
            pre1 = sd1 + xpc1;
        }
        float a0 = (kq == 2) ? tanh_(pre0) : sigf(pre0);
        float a1 = (kq == 2) ? tanh_(pre1) : sigf(pre1);

        // ---- allgather activations across kq ----
        float x10 = __shfl_xor_sync(0xffffffffu, a0, 2);
        float x20 = __shfl_xor_sync(0xffffffffu, a0, 4);
        float x30 = __shfl_xor_sync(0xffffffffu, x10, 4);
        float x11 = __shfl_xor_sync(0xffffffffu, a1, 2);
        float x21 = __shfl_xor_sync(0xffffffffu, a1, 4);
        float x31 = __shfl_xor_sync(0xffffffffu, x11, 4);

        float iv0 = pick(kq, a0, x10, x20, x30);
        float fv0 = pick(1 ^ kq, a0, x10, x20, x30);
        float gv0 = pick(2 ^ kq, a0, x10, x20, x30);
        float ov0 = pick(3 ^ kq, a0, x10, x20, x30);
        float iv1 = pick(kq, a1, x11, x21, x31);
        float fv1 = pick(1 ^ kq, a1, x11, x21, x31);
        float gv1 = pick(2 ^ kq, a1, x11, x21, x31);
        float ov1 = pick(3 ^ kq, a1, x11, x21, x31);

        c0 = fv0 * c0 + iv0 * gv0;
        c1 = fv1 * c1 + iv1 * gv1;
        float h0 = ov0 * tanh_(c0);
        float h1 = ov1 * tanh_(c1);

        // ---- stage next-step state (kq==0 lanes own the writes) ----
        if (kq == 0) {
            hs[p ^ 1][bl0][j]     = h0;
            hs[p ^ 1][bl0 + 1][j] = h1;
            if (MODE != 2) {
                dst[((size_t)t * BB + b0 + bl0)     * HID + j] = h0;
                dst[((size_t)t * BB + b0 + bl0 + 1) * HID + j] = h1;
            }
        }
        if (MODE == 0) { if (tid < 16) xsm[p ^ 1][tid] = xnx; }
        xpc0 = xpn0; xpc1 = xpn1;

        __syncthreads();
    }

    if (MODE == 2) {
        // final h is in hs[0] (last write: t=2047, p=1 -> wrote hs[0])
        if (tid < BT * 2) {
            int b = tid >> 1, o = tid & 1;
            float sum = fcb[o];
#pragma unroll
            for (int jj = 0; jj < HID; jj++)
                sum += hs[0][b][jj] * fcw[o * HID + jj];
            out[(b0 + b) * 2 + o] = sum;
        }
    }
}

// ---------------------------------------------------------------------------
// Projection: g_xp[row][4*j+g] = Wih[64g+j,:] . src[row,:] + bias[64g+j]
// rows = S*B. grid=1024 CTAs x 512 threads; 4 src rows per iteration,
// double-buffered smem, 1 barrier/iter. Thread (j, kq, rh): 4 gate rows of j,
// K subset {16m+4kq}, data rows {2rh, 2rh+1}. Butterfly merge over kq;
// duty lane kq writes gate kq -> cols 4j+kq (64B segments, coalesced).
// ---------------------------------------------------------------------------
#define PCTAS 1024
#define PROWS ((SQ * BB) / PCTAS)     // 1024 rows per CTA
#define PRB   4

template <int SRCB>
__global__ void __launch_bounds__(512, 1)
lstm_proj(const float* __restrict__ Wih,
          const float* __restrict__ bih, const float* __restrict__ bhh)
{
    const float* src = (SRCB == 0) ? g_bufA : g_bufB;
    __shared__ __align__(16) float xr[2][PRB][HP];

    const int tid = threadIdx.x;
    const int j   = tid >> 3;
    const int kq  = (tid >> 1) & 3;
    const int rh  = tid & 1;
    const int rl0 = 2 * rh;

    unsigned long long w[4][8];
#pragma unroll
    for (int g = 0; g < 4; g++)
#pragma unroll
        for (int m = 0; m < 4; m++) {
            const float* p = Wih + (size_t)(64 * g + j) * HID + 16 * m + 4 * kq;
            w[g][2 * m]     = *(const unsigned long long*)(p);
            w[g][2 * m + 1] = *(const unsigned long long*)(p + 2);
        }
    const float biask = bih[64 * kq + j] + bhh[64 * kq + j];

    const size_t row0 = (size_t)blockIdx.x * PROWS;

    // preload block 0: 4 rows x 64 floats, threads 0..127 carry float2 each
    float2 ld = make_float2(0.f, 0.f);
    if (tid < 128)
        ld = *(const float2*)(src + (row0 + (tid >> 5)) * HID + 2 * (tid & 31));
    if (tid < 128) *(float2*)(&xr[0][tid >> 5][2 * (tid & 31)]) = ld;
    __syncthreads();

    for (int it = 0; it < PROWS / PRB; it++) {
        const int p = it & 1;
        const size_t rb = row0 + (size_t)it * PRB;

        // prefetch next block into regs
        if (it + 1 < PROWS / PRB && tid < 128)
            ld = *(const float2*)(src + (rb + PRB + (tid >> 5)) * HID + 2 * (tid & 31));

        unsigned long long acc[4][2];
#pragma unroll
        for (int g = 0; g < 4; g++) { acc[g][0] = 0ULL; acc[g][1] = 0ULL; }
#pragma unroll
        for (int m = 0; m < 4; m++) {
            ulonglong2 r0v = *(const ulonglong2*)(&xr[p][rl0][16 * m + 4 * kq]);
            ulonglong2 r1v = *(const ulonglong2*)(&xr[p][rl0 + 1][16 * m + 4 * kq]);
#pragma unroll
            for (int g = 0; g < 4; g++) {
                acc[g][0] = fma2(w[g][2 * m], r0v.x, acc[g][0]);
                acc[g][0] = fma2(w[g][2 * m + 1], r0v.y, acc[g][0]);
                acc[g][1] = fma2(w[g][2 * m], r1v.x, acc[g][1]);
                acc[g][1] = fma2(w[g][2 * m + 1], r1v.y, acc[g][1]);
            }
        }

        float s[4][2];
#pragma unroll
        for (int g = 0; g < 4; g++)
#pragma unroll
            for (int i = 0; i < 2; i++) {
                float v = lohi(acc[g][i]);
                v += __shfl_xor_sync(0xffffffffu, v, 2);
                v += __shfl_xor_sync(0xffffffffu, v, 4);
                s[g][i] = v;
            }

        // duty gate kq for both data rows
        float sd0 = pick(kq, s[0][0], s[1][0], s[2][0], s[3][0]) + biask;
        float sd1 = pick(kq, s[0][1], s[1][1], s[2][1], s[3][1]) + biask;
        g_xp[(rb + rl0)     * 256 + 4 * j + kq] = sd0;
        g_xp[(rb + rl0 + 1) * 256 + 4 * j + kq] = sd1;

        // stage next block
        if (it + 1 < PROWS / PRB && tid < 128)
            *(float2*)(&xr[p ^ 1][tid >> 5][2 * (tid & 31)]) = ld;
        __syncthreads();
    }
}

extern "C" void kernel_launch(void* const* d_in, const int* in_sizes, int n_in,
                              void* d_out, int out_size)
{
    (void)in_sizes; (void)n_in; (void)out_size;
    const float* x    = (const float*)d_in[0];
    const float* Wih0 = (const float*)d_in[1];
    const float* Whh0 = (const float*)d_in[2];
    const float* bih0 = (const float*)d_in[3];
    const float* bhh0 = (const float*)d_in[4];
    const float* Wih1 = (const float*)d_in[5];
    const float* Whh1 = (const float*)d_in[6];
    const float* bih1 = (const float*)d_in[7];
    const float* bhh1 = (const float*)d_in[8];
    const float* Wih2 = (const float*)d_in[9];
    const float* Whh2 = (const float*)d_in[10];
    const float* bih2 = (const float*)d_in[11];
    const float* bhh2 = (const float*)d_in[12];
    const float* fc_w = (const float*)d_in[13];
    const float* fc_b = (const float*)d_in[14];
    float* out = (float*)d_out;

    dim3 rgrid(BB / BT), rblock(512);
    dim3 pgrid(PCTAS), pblock(512);

    lstm_rec<0><<<rgrid, rblock>>>(x, Wih0, Whh0, bih0, bhh0, nullptr, nullptr, nullptr);
    lstm_proj<0><<<pgrid, pblock>>>(Wih1, bih1, bhh1);
    lstm_rec<1><<<rgrid, rblock>>>(nullptr, nullptr, Whh1, nullptr, nullptr, nullptr, nullptr, nullptr);
    lstm_proj<1><<<pgrid, pblock>>>(Wih2, bih2, bhh2);
    lstm_rec<2><<<rgrid, rblock>>>(nullptr, nullptr, Whh2, nullptr, nullptr, fc_w, fc_b, out);
}